// round 13
// baseline (speedup 1.0000x reference)
#include <cuda_runtime.h>
#include <cuda_bf16.h>
#include <math.h>
#include <stdint.h>

// Problem constants
#define BB   8
#define SEQL 4096
#define QL   1024
#define CIN  256
#define KVD  640
#define QD   128
#define HH   8
#define KD   16
#define VD   64
#define COUT 512
#define EPSB 1e-3f

// Intermediates as __device__ globals (no dynamic allocation allowed)
__device__ __nv_bfloat16 d_Kb[BB * HH * SEQL * KD];   // K bf16 [b][h][seq][16]
__device__ __nv_bfloat16 d_Vt[BB * HH * VD * SEQL];   // V bf16 transposed [b][h][dim][seq]
__device__ float d_qbuf [BB * QL * QD];               // [B, QLEN, 128] (BN folded)
__device__ float d_zbuf [BB * QL * COUT];             // attention out, TF-reshaped

__device__ __forceinline__ float ex2(float x) {
    float y;
    asm("ex2.approx.ftz.f32 %0, %1;" : "=f"(y) : "f"(x));
    return y;
}
__device__ __forceinline__ uint32_t s2u(const void* p) {
    return (uint32_t)__cvta_generic_to_shared(p);
}
__device__ __forceinline__ void cpasync16(uint32_t dst, const void* src) {
    asm volatile("cp.async.cg.shared.global [%0], [%1], 16;" :: "r"(dst), "l"(src));
}
#define CP_COMMIT() asm volatile("cp.async.commit_group;")
#define CP_WAIT1()  asm volatile("cp.async.wait_group 1;")

// tf32 round-to-nearest conversion
__device__ __forceinline__ uint32_t f2tf32(float x) {
    uint32_t r;
    asm("cvt.rna.tf32.f32 %0, %1;" : "=r"(r) : "f"(x));
    return r;
}
__device__ __forceinline__ float tf32r(float x) {
    return __uint_as_float(f2tf32(x));
}
// m16n8k8 tf32 MMA, D = A*B + D
__device__ __forceinline__ void mma_tf32(float& c0, float& c1, float& c2, float& c3,
                                         uint32_t a0, uint32_t a1, uint32_t a2, uint32_t a3,
                                         uint32_t b0, uint32_t b1) {
    asm volatile("mma.sync.aligned.m16n8k8.row.col.f32.tf32.tf32.f32 "
                 "{%0,%1,%2,%3}, {%4,%5,%6,%7}, {%8,%9}, {%0,%1,%2,%3};"
                 : "+f"(c0), "+f"(c1), "+f"(c2), "+f"(c3)
                 : "r"(a0), "r"(a1), "r"(a2), "r"(a3), "r"(b0), "r"(b1));
}
// m16n8k16 bf16 MMA, D = A*B + D
__device__ __forceinline__ void mma_bf16(float& c0, float& c1, float& c2, float& c3,
                                         uint32_t a0, uint32_t a1, uint32_t a2, uint32_t a3,
                                         uint32_t b0, uint32_t b1) {
    asm volatile("mma.sync.aligned.m16n8k16.row.col.f32.bf16.bf16.f32 "
                 "{%0,%1,%2,%3}, {%4,%5,%6,%7}, {%8,%9}, {%0,%1,%2,%3};"
                 : "+f"(c0), "+f"(c1), "+f"(c2), "+f"(c3)
                 : "r"(a0), "r"(a1), "r"(a2), "r"(a3), "r"(b0), "r"(b1));
}
__device__ __forceinline__ uint32_t packbf(float lo, float hi) {
    __nv_bfloat162 p = __floats2bfloat162_rn(lo, hi);
    return *(uint32_t*)&p;
}
__device__ __forceinline__ float hswish(float x) {
    return x * __saturatef(x * (1.0f / 6.0f) + 0.5f);
}

// ---------------------------------------------------------------------------
// tf32 tensor-core GEMM, register-prefetch pipelined, BN applied in epilogue.
// BM=128, BN=128, BK=16, 256 threads (8 warps as 4m x 2n, warp tile 32x64).
// MODE 0: kv (A=x) -> epilogue scatters K (bf16, [b][h][seq][16]) and
//         V-transposed (bf16, [b][h][dim][seq]).
// MODE 1: q (A=x strided gather) -> d_qbuf fp32.
// ---------------------------------------------------------------------------
template <int MODE>
__global__ __launch_bounds__(256) void tgemm_kernel(const float* __restrict__ A,
                                                    const float* __restrict__ W,
                                                    const float* __restrict__ bia,
                                                    const float* __restrict__ gam,
                                                    const float* __restrict__ bet,
                                                    const float* __restrict__ mu,
                                                    const float* __restrict__ var,
                                                    int M, int N, int K) {
    __shared__ __align__(16) float Ah[16][132];
    __shared__ __align__(16) float Bh[16][132];

    int tid  = threadIdx.x;
    int m0 = blockIdx.y * 128;
    int n0 = blockIdx.x * 128;
    int w = tid >> 5, lane = tid & 31;
    int g = lane >> 2, tg = lane & 3;
    int wm = w >> 1, wn = w & 1;

    float acc[2][8][4];
#pragma unroll
    for (int i = 0; i < 2; i++)
#pragma unroll
        for (int j = 0; j < 8; j++)
#pragma unroll
            for (int e = 0; e < 4; e++) acc[i][j][e] = 0.0f;

    int lrow[2], lc4[2];
    const float* aptr[2];
#pragma unroll
    for (int j = 0; j < 2; j++) {
        int idx = tid + j * 256;
        int r = idx >> 2, c4 = idx & 3;
        lrow[j] = r; lc4[j] = c4;
        int gr = m0 + r;
        int src;
        if (MODE == 1) {
            int bb = gr >> 10, ql = gr & 1023;
            int qy = ql >> 5, qx = ql & 31;
            src = (bb << 12) + (qy << 7) + (qx << 1);
        } else {
            src = gr;
        }
        aptr[j] = A + (size_t)src * K + c4 * 4;
    }
    int bkr[2], bnc[2];
    const float* bptr[2];
#pragma unroll
    for (int j = 0; j < 2; j++) {
        int idx = tid + j * 256;
        bkr[j] = idx >> 5; bnc[j] = (idx & 31) * 4;
        bptr[j] = W + (size_t)bkr[j] * N + n0 + bnc[j];
    }

    float4 aReg[2], bReg[2];
#pragma unroll
    for (int j = 0; j < 2; j++) {
        aReg[j] = *(const float4*)(aptr[j]);
        bReg[j] = *(const float4*)(bptr[j]);
    }

    const int NT = K / 16;
    for (int t = 0; t < NT; ++t) {
#pragma unroll
        for (int j = 0; j < 2; j++) {
            float4 a = aReg[j];
            float av[4] = {a.x, a.y, a.z, a.w};
#pragma unroll
            for (int e = 0; e < 4; e++)
                Ah[lc4[j] * 4 + e][lrow[j]] = tf32r(av[e]);
            float4 b = bReg[j];
            float4 h4 = {tf32r(b.x), tf32r(b.y), tf32r(b.z), tf32r(b.w)};
            *(float4*)&Bh[bkr[j]][bnc[j]] = h4;
        }
        __syncthreads();

        if (t + 1 < NT) {
            int k0 = (t + 1) * 16;
#pragma unroll
            for (int j = 0; j < 2; j++) {
                aReg[j] = *(const float4*)(aptr[j] + k0);
                bReg[j] = *(const float4*)(bptr[j] + (size_t)k0 * N);
            }
        }

#pragma unroll
        for (int k8 = 0; k8 < 16; k8 += 8) {
            uint32_t ah[2][4];
#pragma unroll
            for (int mi = 0; mi < 2; mi++) {
                int r = wm * 32 + mi * 16 + g;
                ah[mi][0] = __float_as_uint(Ah[k8 + tg][r]);
                ah[mi][1] = __float_as_uint(Ah[k8 + tg][r + 8]);
                ah[mi][2] = __float_as_uint(Ah[k8 + tg + 4][r]);
                ah[mi][3] = __float_as_uint(Ah[k8 + tg + 4][r + 8]);
            }
#pragma unroll
            for (int nj = 0; nj < 8; nj++) {
                int n = wn * 64 + nj * 8 + g;
                uint32_t bh0 = __float_as_uint(Bh[k8 + tg][n]);
                uint32_t bh1 = __float_as_uint(Bh[k8 + tg + 4][n]);
#pragma unroll
                for (int mi = 0; mi < 2; mi++)
                    mma_tf32(acc[mi][nj][0], acc[mi][nj][1], acc[mi][nj][2], acc[mi][nj][3],
                             ah[mi][0], ah[mi][1], ah[mi][2], ah[mi][3], bh0, bh1);
            }
        }
        __syncthreads();
    }

    // epilogue with BN: out = acc*s + ((b-mu)*s + beta)
#pragma unroll
    for (int nj = 0; nj < 8; nj++) {
        int col = n0 + wn * 64 + nj * 8 + 2 * tg;
        float s0 = gam[col] * rsqrtf(var[col] + EPSB);
        float s1 = gam[col + 1] * rsqrtf(var[col + 1] + EPSB);
        float c0 = (bia[col] - mu[col]) * s0 + bet[col];
        float c1 = (bia[col + 1] - mu[col + 1]) * s1 + bet[col + 1];
#pragma unroll
        for (int mi = 0; mi < 2; mi++) {
            int row = m0 + wm * 32 + mi * 16 + g;
            float v00 = acc[mi][nj][0] * s0 + c0, v01 = acc[mi][nj][1] * s1 + c1;   // row
            float v10 = acc[mi][nj][2] * s0 + c0, v11 = acc[mi][nj][3] * s1 + c1;   // row+8
            if (MODE == 0) {
                int bb = row >> 12, seq = row & 4095;
                int hh = col / 80, c = col - hh * 80;
                if (c < KD) {
                    __nv_bfloat162 p0 = __floats2bfloat162_rn(v00, v01);
                    __nv_bfloat162 p1 = __floats2bfloat162_rn(v10, v11);
                    size_t kbase = ((size_t)(bb * HH + hh) * SEQL + seq) * KD + c;
                    *(__nv_bfloat162*)&d_Kb[kbase] = p0;
                    *(__nv_bfloat162*)&d_Kb[kbase + 8 * KD] = p1;
                } else {
                    int dd = c - KD;
                    size_t vbase = ((size_t)(bb * HH + hh) * VD + dd) * SEQL + seq;
                    d_Vt[vbase]            = __float2bfloat16_rn(v00);
                    d_Vt[vbase + SEQL]     = __float2bfloat16_rn(v01);
                    d_Vt[vbase + 8]        = __float2bfloat16_rn(v10);
                    d_Vt[vbase + SEQL + 8] = __float2bfloat16_rn(v11);
                }
            } else {
                float2 o0 = {v00, v01};
                float2 o1 = {v10, v11};
                *(float2*)(d_qbuf + (size_t)row * N + col) = o0;
                *(float2*)(d_qbuf + (size_t)(row + 8) * N + col) = o1;
            }
        }
    }
}

// ---------------------------------------------------------------------------
// proj GEMM: out = BN(hswish(zbuf) @ Wp + b), split-bf16 3-term
// (hi*hi + hi*lo + lo*hi with m16n8k16) for near-fp32 accuracy at half the
// mma and LDS cost of 3xTF32. BM=128, BN=128, BK=16, 256 threads.
// Smem: A [m][k] bf16 rows of 24 (48B stride, conflict-free 12g+tg banks);
//       B [n][k] bf16 transposed, same stride.
// ---------------------------------------------------------------------------
__global__ __launch_bounds__(256) void bgemm_kernel(const float* __restrict__ W,
                                                    const float* __restrict__ bia,
                                                    const float* __restrict__ gam,
                                                    const float* __restrict__ bet,
                                                    const float* __restrict__ mu,
                                                    const float* __restrict__ var,
                                                    float* __restrict__ C) {
    const int N = COUT, K = COUT;
    __shared__ __align__(16) __nv_bfloat16 Ahs[128][24];
    __shared__ __align__(16) __nv_bfloat16 Als[128][24];
    __shared__ __align__(16) __nv_bfloat16 Bhs[128][24];
    __shared__ __align__(16) __nv_bfloat16 Bls[128][24];

    const float* A = d_zbuf;
    int tid  = threadIdx.x;
    int m0 = blockIdx.y * 128;
    int n0 = blockIdx.x * 128;
    int w = tid >> 5, lane = tid & 31;
    int g = lane >> 2, tg = lane & 3;
    int wm = w >> 1, wn = w & 1;

    float acc[2][8][4];
#pragma unroll
    for (int i = 0; i < 2; i++)
#pragma unroll
        for (int j = 0; j < 8; j++)
#pragma unroll
            for (int e = 0; e < 4; e++) acc[i][j][e] = 0.0f;

    int lrow[2], lc4[2];
    const float* aptr[2];
#pragma unroll
    for (int j = 0; j < 2; j++) {
        int idx = tid + j * 256;
        lrow[j] = idx >> 2; lc4[j] = idx & 3;
        aptr[j] = A + (size_t)(m0 + lrow[j]) * K + lc4[j] * 4;
    }
    int bkr[2], bnc[2];
    const float* bptr[2];
#pragma unroll
    for (int j = 0; j < 2; j++) {
        int idx = tid + j * 256;
        bkr[j] = idx >> 5; bnc[j] = (idx & 31) * 4;
        bptr[j] = W + (size_t)bkr[j] * N + n0 + bnc[j];
    }

    float4 aReg[2], bReg[2];
#pragma unroll
    for (int j = 0; j < 2; j++) {
        aReg[j] = *(const float4*)(aptr[j]);
        bReg[j] = *(const float4*)(bptr[j]);
    }

    const int NT = K / 16;   // 32 k16 tiles
    for (int t = 0; t < NT; ++t) {
#pragma unroll
        for (int j = 0; j < 2; j++) {
            float4 a = aReg[j];
            float av[4] = {hswish(a.x), hswish(a.y), hswish(a.z), hswish(a.w)};
            __nv_bfloat162 h01 = __floats2bfloat162_rn(av[0], av[1]);
            __nv_bfloat162 h23 = __floats2bfloat162_rn(av[2], av[3]);
            __nv_bfloat162 l01 = __floats2bfloat162_rn(av[0] - __bfloat162float(h01.x),
                                                       av[1] - __bfloat162float(h01.y));
            __nv_bfloat162 l23 = __floats2bfloat162_rn(av[2] - __bfloat162float(h23.x),
                                                       av[3] - __bfloat162float(h23.y));
            *(__nv_bfloat162*)&Ahs[lrow[j]][lc4[j] * 4]     = h01;
            *(__nv_bfloat162*)&Ahs[lrow[j]][lc4[j] * 4 + 2] = h23;
            *(__nv_bfloat162*)&Als[lrow[j]][lc4[j] * 4]     = l01;
            *(__nv_bfloat162*)&Als[lrow[j]][lc4[j] * 4 + 2] = l23;

            float4 b = bReg[j];
            float bv[4] = {b.x, b.y, b.z, b.w};
#pragma unroll
            for (int i = 0; i < 4; i++) {
                __nv_bfloat16 h = __float2bfloat16_rn(bv[i]);
                Bhs[bnc[j] + i][bkr[j]] = h;
                Bls[bnc[j] + i][bkr[j]] = __float2bfloat16_rn(bv[i] - __bfloat162float(h));
            }
        }
        __syncthreads();

        if (t + 1 < NT) {
            int k0 = (t + 1) * 16;
#pragma unroll
            for (int j = 0; j < 2; j++) {
                aReg[j] = *(const float4*)(aptr[j] + k0);
                bReg[j] = *(const float4*)(bptr[j] + (size_t)k0 * N);
            }
        }

        uint32_t ah[2][4], al[2][4];
#pragma unroll
        for (int mi = 0; mi < 2; mi++) {
            int r = wm * 32 + mi * 16 + g;
            ah[mi][0] = *(const uint32_t*)&Ahs[r][2 * tg];
            ah[mi][1] = *(const uint32_t*)&Ahs[r + 8][2 * tg];
            ah[mi][2] = *(const uint32_t*)&Ahs[r][8 + 2 * tg];
            ah[mi][3] = *(const uint32_t*)&Ahs[r + 8][8 + 2 * tg];
            al[mi][0] = *(const uint32_t*)&Als[r][2 * tg];
            al[mi][1] = *(const uint32_t*)&Als[r + 8][2 * tg];
            al[mi][2] = *(const uint32_t*)&Als[r][8 + 2 * tg];
            al[mi][3] = *(const uint32_t*)&Als[r + 8][8 + 2 * tg];
        }
#pragma unroll
        for (int nj = 0; nj < 8; nj++) {
            int n = wn * 64 + nj * 8 + g;
            uint32_t bh0 = *(const uint32_t*)&Bhs[n][2 * tg];
            uint32_t bh1 = *(const uint32_t*)&Bhs[n][8 + 2 * tg];
            uint32_t bl0 = *(const uint32_t*)&Bls[n][2 * tg];
            uint32_t bl1 = *(const uint32_t*)&Bls[n][8 + 2 * tg];
#pragma unroll
            for (int mi = 0; mi < 2; mi++) {
                mma_bf16(acc[mi][nj][0], acc[mi][nj][1], acc[mi][nj][2], acc[mi][nj][3],
                         ah[mi][0], ah[mi][1], ah[mi][2], ah[mi][3], bh0, bh1);
                mma_bf16(acc[mi][nj][0], acc[mi][nj][1], acc[mi][nj][2], acc[mi][nj][3],
                         ah[mi][0], ah[mi][1], ah[mi][2], ah[mi][3], bl0, bl1);
                mma_bf16(acc[mi][nj][0], acc[mi][nj][1], acc[mi][nj][2], acc[mi][nj][3],
                         al[mi][0], al[mi][1], al[mi][2], al[mi][3], bh0, bh1);
            }
        }
        __syncthreads();
    }

#pragma unroll
    for (int nj = 0; nj < 8; nj++) {
        int col = n0 + wn * 64 + nj * 8 + 2 * tg;
        float s0 = gam[col] * rsqrtf(var[col] + EPSB);
        float s1 = gam[col + 1] * rsqrtf(var[col + 1] + EPSB);
        float c0 = (bia[col] - mu[col]) * s0 + bet[col];
        float c1 = (bia[col + 1] - mu[col + 1]) * s1 + bet[col + 1];
#pragma unroll
        for (int mi = 0; mi < 2; mi++) {
            int row = m0 + wm * 32 + mi * 16 + g;
            float2 o0 = {acc[mi][nj][0] * s0 + c0, acc[mi][nj][1] * s1 + c1};
            float2 o1 = {acc[mi][nj][2] * s0 + c0, acc[mi][nj][3] * s1 + c1};
            *(float2*)(C + (size_t)row * N + col) = o0;
            *(float2*)(C + (size_t)(row + 8) * N + col) = o1;
        }
    }
}

// ---------------------------------------------------------------------------
// Flash attention via bf16 mma.sync (m16n8k16) — unchanged from R12.
// ---------------------------------------------------------------------------
__global__ __launch_bounds__(128) void attn_kernel() {
    __shared__ __align__(16) __nv_bfloat16 Ks[2][32][24];
    __shared__ __align__(16) __nv_bfloat16 Vs[2][64][40];

    int tid = threadIdx.x;
    int b = blockIdx.z, h = blockIdx.y;
    int q0 = blockIdx.x * 64;
    int w = tid >> 5;
    int lane = tid & 31;
    int g = lane >> 2, tg = lane & 3;

    const __nv_bfloat16* Kg = d_Kb + (size_t)(b * HH + h) * SEQL * KD;
    const __nv_bfloat16* Vg = d_Vt + (size_t)(b * HH + h) * VD * SEQL;

    const __nv_bfloat16* kgp = nullptr;
    uint32_t ksm[2] = {0, 0};
    if (tid < 64) {
        int r = tid >> 1, o = (tid & 1) * 8;
        kgp = Kg + (size_t)r * KD + o;
        ksm[0] = s2u(&Ks[0][r][o]);
        ksm[1] = s2u(&Ks[1][r][o]);
    }
    const __nv_bfloat16* vgp[2];
    uint32_t vsm[2][2];
#pragma unroll
    for (int j = 0; j < 2; j++) {
        int idx = tid + j * 128;
        int r = idx >> 2, o = (idx & 3) * 8;
        vgp[j] = Vg + (size_t)r * SEQL + o;
        vsm[0][j] = s2u(&Vs[0][r][o]);
        vsm[1][j] = s2u(&Vs[1][r][o]);
    }

    const float SC = 0.25f * 1.44269504088896340736f;
    int qA = q0 + w * 16 + g;
    int qB = qA + 8;
    const float* qp0 = d_qbuf + (size_t)(b * QL + qA) * QD + h * KD;
    const float* qp1 = d_qbuf + (size_t)(b * QL + qB) * QD + h * KD;
    uint32_t qa[4];
    qa[0] = packbf(qp0[2 * tg] * SC,     qp0[2 * tg + 1] * SC);
    qa[1] = packbf(qp1[2 * tg] * SC,     qp1[2 * tg + 1] * SC);
    qa[2] = packbf(qp0[8 + 2 * tg] * SC, qp0[8 + 2 * tg + 1] * SC);
    qa[3] = packbf(qp1[8 + 2 * tg] * SC, qp1[8 + 2 * tg + 1] * SC);

    float acc[8][4];
#pragma unroll
    for (int i = 0; i < 8; i++)
#pragma unroll
        for (int j = 0; j < 4; j++) acc[i][j] = 0.0f;
    float l0 = 0.0f, l1 = 0.0f;

    if (tid < 64) cpasync16(ksm[0], kgp);
#pragma unroll
    for (int j = 0; j < 2; j++) cpasync16(vsm[0][j], vgp[j]);
    CP_COMMIT();

    const int NT = SEQL / 32;
    for (int t = 0; t < NT; ++t) {
        if (t + 1 < NT) {
            int koff = (t + 1) * 32;
            int nbf = (t + 1) & 1;
            if (tid < 64) cpasync16(ksm[nbf], kgp + (size_t)koff * KD);
#pragma unroll
            for (int j = 0; j < 2; j++) cpasync16(vsm[nbf][j], vgp[j] + koff);
        }
        CP_COMMIT();
        CP_WAIT1();
        __syncthreads();

        const int bf = t & 1;
#pragma unroll
        for (int kg16 = 0; kg16 < 2; kg16++) {
            const int kr = kg16 * 16;
            uint32_t kb0 = *(const uint32_t*)&Ks[bf][kr + g][2 * tg];
            uint32_t kb1 = *(const uint32_t*)&Ks[bf][kr + g][8 + 2 * tg];
            float c0 = 0.f, c1 = 0.f, c2 = 0.f, c3 = 0.f;
            mma_bf16(c0, c1, c2, c3, qa[0], qa[1], qa[2], qa[3], kb0, kb1);
            uint32_t kb2 = *(const uint32_t*)&Ks[bf][kr + 8 + g][2 * tg];
            uint32_t kb3 = *(const uint32_t*)&Ks[bf][kr + 8 + g][8 + 2 * tg];
            float d0 = 0.f, d1 = 0.f, d2 = 0.f, d3 = 0.f;
            mma_bf16(d0, d1, d2, d3, qa[0], qa[1], qa[2], qa[3], kb2, kb3);

            float p00 = ex2(c0), p01 = ex2(c1), p02 = ex2(c2), p03 = ex2(c3);
            float p10 = ex2(d0), p11 = ex2(d1), p12 = ex2(d2), p13 = ex2(d3);
            l0 += (p00 + p01) + (p10 + p11);
            l1 += (p02 + p03) + (p12 + p13);

            uint32_t a0 = packbf(p00, p01);
            uint32_t a1 = packbf(p02, p03);
            uint32_t a2 = packbf(p10, p11);
            uint32_t a3 = packbf(p12, p13);
#pragma unroll
            for (int nt = 0; nt < 8; nt++) {
                uint32_t vb0 = *(const uint32_t*)&Vs[bf][8 * nt + g][kr + 2 * tg];
                uint32_t vb1 = *(const uint32_t*)&Vs[bf][8 * nt + g][kr + 8 + 2 * tg];
                mma_bf16(acc[nt][0], acc[nt][1], acc[nt][2], acc[nt][3],
                         a0, a1, a2, a3, vb0, vb1);
            }
        }
        __syncthreads();
    }

    l0 += __shfl_xor_sync(0xffffffffu, l0, 1);
    l0 += __shfl_xor_sync(0xffffffffu, l0, 2);
    l1 += __shfl_xor_sync(0xffffffffu, l1, 1);
    l1 += __shfl_xor_sync(0xffffffffu, l1, 2);
    float r0 = 1.0f / l0, r1 = 1.0f / l1;

    float* zb = d_zbuf + (size_t)b * QL * COUT;
    int colA = qA & 511, hiA = qA >> 9;
    int colB = qB & 511, hiB = qB >> 9;
#pragma unroll
    for (int nt = 0; nt < 8; nt++) {
#pragma unroll
        for (int e = 0; e < 2; e++) {
            int d = 8 * nt + 2 * tg + e;
            zb[(size_t)(h * 128 + 2 * d + hiA) * COUT + colA] = acc[nt][e] * r0;
            zb[(size_t)(h * 128 + 2 * d + hiB) * COUT + colB] = acc[nt][2 + e] * r1;
        }
    }
}

// ---------------------------------------------------------------------------
// Launch
// ---------------------------------------------------------------------------
extern "C" void kernel_launch(void* const* d_in, const int* in_sizes, int n_in,
                              void* d_out, int out_size) {
    const float* x    = (const float*)d_in[0];
    const float* Wkv  = (const float*)d_in[1];
    const float* bkv  = (const float*)d_in[2];
    const float* gkv  = (const float*)d_in[3];
    const float* bekv = (const float*)d_in[4];
    const float* mkv  = (const float*)d_in[5];
    const float* vkv  = (const float*)d_in[6];
    const float* Wq   = (const float*)d_in[7];
    const float* bq   = (const float*)d_in[8];
    const float* gq   = (const float*)d_in[9];
    const float* beq  = (const float*)d_in[10];
    const float* mq   = (const float*)d_in[11];
    const float* vq   = (const float*)d_in[12];
    const float* Wp   = (const float*)d_in[13];
    const float* bp   = (const float*)d_in[14];
    const float* gp   = (const float*)d_in[15];
    const float* bep  = (const float*)d_in[16];
    const float* mp   = (const float*)d_in[17];
    const float* vp   = (const float*)d_in[18];
    float* out = (float*)d_out;

    // kv = BN(x @ Wkv + b) -> K (bf16) + V-transposed (bf16), BN in epilogue
    tgemm_kernel<0><<<dim3(KVD / 128, (BB * SEQL) / 128), 256>>>(
        x, Wkv, bkv, gkv, bekv, mkv, vkv, BB * SEQL, KVD, CIN);
    // q = BN(xq @ Wq + b) -> fp32, BN in epilogue
    tgemm_kernel<1><<<dim3(QD / 128, (BB * QL) / 128), 256>>>(
        x, Wq, bq, gq, beq, mq, vq, BB * QL, QD, CIN);
    // fused flash attention (bf16 mma) -> d_zbuf (TF-reshaped)
    attn_kernel<<<dim3(QL / 64, HH, BB), 128>>>();
    // out = BN(hswish(zbuf) @ Wp + b), split-bf16 3-term
    bgemm_kernel<<<dim3(COUT / 128, (BB * QL) / 128), 256>>>(
        Wp, bp, gp, bep, mp, vp, out);
}

// round 15
// speedup vs baseline: 1.0276x; 1.0276x over previous
#include <cuda_runtime.h>
#include <cuda_bf16.h>
#include <math.h>
#include <stdint.h>

// Problem constants
#define BB   8
#define SEQL 4096
#define QL   1024
#define CIN  256
#define KVD  640
#define QD   128
#define HH   8
#define KD   16
#define VD   64
#define COUT 512
#define EPSB 1e-3f

// Intermediates as __device__ globals (no dynamic allocation allowed)
__device__ __nv_bfloat16 d_Kb[BB * HH * SEQL * KD];   // K bf16 [b][h][seq][16]
__device__ __nv_bfloat16 d_Vt[BB * HH * VD * SEQL];   // V bf16 transposed [b][h][dim][seq]
__device__ float d_qbuf [BB * QL * QD];               // [B, QLEN, 128] (BN folded)
__device__ float d_zbuf [BB * QL * COUT];             // attention out, TF-reshaped

__device__ __forceinline__ float ex2(float x) {
    float y;
    asm("ex2.approx.ftz.f32 %0, %1;" : "=f"(y) : "f"(x));
    return y;
}
__device__ __forceinline__ uint32_t s2u(const void* p) {
    return (uint32_t)__cvta_generic_to_shared(p);
}
__device__ __forceinline__ void cpasync16(uint32_t dst, const void* src) {
    asm volatile("cp.async.cg.shared.global [%0], [%1], 16;" :: "r"(dst), "l"(src));
}
#define CP_COMMIT() asm volatile("cp.async.commit_group;")
#define CP_WAIT1()  asm volatile("cp.async.wait_group 1;")

__device__ __forceinline__ uint32_t f2tf32(float x) {
    uint32_t r;
    asm("cvt.rna.tf32.f32 %0, %1;" : "=r"(r) : "f"(x));
    return r;
}
__device__ __forceinline__ float tf32r(float x) {
    return __uint_as_float(f2tf32(x));
}
// m16n8k8 tf32 MMA, D = A*B + D
__device__ __forceinline__ void mma_tf32(float& c0, float& c1, float& c2, float& c3,
                                         uint32_t a0, uint32_t a1, uint32_t a2, uint32_t a3,
                                         uint32_t b0, uint32_t b1) {
    asm volatile("mma.sync.aligned.m16n8k8.row.col.f32.tf32.tf32.f32 "
                 "{%0,%1,%2,%3}, {%4,%5,%6,%7}, {%8,%9}, {%0,%1,%2,%3};"
                 : "+f"(c0), "+f"(c1), "+f"(c2), "+f"(c3)
                 : "r"(a0), "r"(a1), "r"(a2), "r"(a3), "r"(b0), "r"(b1));
}
// m16n8k16 bf16 MMA, D = A*B + D
__device__ __forceinline__ void mma_bf16(float& c0, float& c1, float& c2, float& c3,
                                         uint32_t a0, uint32_t a1, uint32_t a2, uint32_t a3,
                                         uint32_t b0, uint32_t b1) {
    asm volatile("mma.sync.aligned.m16n8k16.row.col.f32.bf16.bf16.f32 "
                 "{%0,%1,%2,%3}, {%4,%5,%6,%7}, {%8,%9}, {%0,%1,%2,%3};"
                 : "+f"(c0), "+f"(c1), "+f"(c2), "+f"(c3)
                 : "r"(a0), "r"(a1), "r"(a2), "r"(a3), "r"(b0), "r"(b1));
}
__device__ __forceinline__ uint32_t packbf(float lo, float hi) {
    __nv_bfloat162 p = __floats2bfloat162_rn(lo, hi);
    return *(uint32_t*)&p;
}
__device__ __forceinline__ float hswish(float x) {
    return x * __saturatef(x * (1.0f / 6.0f) + 0.5f);
}

// ---------------------------------------------------------------------------
// tf32 tensor-core GEMM, register-prefetch pipelined, BN in epilogue.
// BM=128, BN=128, BK=16, 256 threads (8 warps: 4m x 2n, warp tile 32x64).
// MODE 0: kv (A=Ain=x) -> scatter K (bf16) + V-transposed (bf16).
// MODE 1: q (A=Ain=x strided gather) -> d_qbuf fp32.
// MODE 2: proj (A = d_zbuf selected IN DEVICE CODE, hswish), THREE=1 (3xTF32)
//         -> Cout fp32.  (Host must NOT pass d_zbuf — device-global address
//         is only valid device-side.)
// ---------------------------------------------------------------------------
template <int MODE, int THREE>
__global__ __launch_bounds__(256) void tgemm_kernel(const float* __restrict__ Ain,
                                                    const float* __restrict__ W,
                                                    const float* __restrict__ bia,
                                                    const float* __restrict__ gam,
                                                    const float* __restrict__ bet,
                                                    const float* __restrict__ mu,
                                                    const float* __restrict__ var,
                                                    float* __restrict__ Cout,
                                                    int M, int N, int K) {
    const float* A = (MODE == 2) ? d_zbuf : Ain;

    __shared__ __align__(16) float Ah[16][132];
    __shared__ __align__(16) float Bh[16][132];
    __shared__ __align__(16) float Al[THREE ? 16 : 1][THREE ? 132 : 4];
    __shared__ __align__(16) float Bl[THREE ? 16 : 1][THREE ? 132 : 4];

    int tid  = threadIdx.x;
    int m0 = blockIdx.y * 128;
    int n0 = blockIdx.x * 128;
    int w = tid >> 5, lane = tid & 31;
    int g = lane >> 2, tg = lane & 3;
    int wm = w >> 1, wn = w & 1;

    float acc[2][8][4];
#pragma unroll
    for (int i = 0; i < 2; i++)
#pragma unroll
        for (int j = 0; j < 8; j++)
#pragma unroll
            for (int e = 0; e < 4; e++) acc[i][j][e] = 0.0f;

    int lrow[2], lc4[2];
    const float* aptr[2];
#pragma unroll
    for (int j = 0; j < 2; j++) {
        int idx = tid + j * 256;
        int r = idx >> 2, c4 = idx & 3;
        lrow[j] = r; lc4[j] = c4;
        int gr = m0 + r;
        int src;
        if (MODE == 1) {
            int bb = gr >> 10, ql = gr & 1023;
            int qy = ql >> 5, qx = ql & 31;
            src = (bb << 12) + (qy << 7) + (qx << 1);
        } else {
            src = gr;
        }
        aptr[j] = A + (size_t)src * K + c4 * 4;
    }
    int bkr[2], bnc[2];
    const float* bptr[2];
#pragma unroll
    for (int j = 0; j < 2; j++) {
        int idx = tid + j * 256;
        bkr[j] = idx >> 5; bnc[j] = (idx & 31) * 4;
        bptr[j] = W + (size_t)bkr[j] * N + n0 + bnc[j];
    }

    float4 aReg[2], bReg[2];
#pragma unroll
    for (int j = 0; j < 2; j++) {
        aReg[j] = *(const float4*)(aptr[j]);
        bReg[j] = *(const float4*)(bptr[j]);
    }

    const int NT = K / 16;
    for (int t = 0; t < NT; ++t) {
#pragma unroll
        for (int j = 0; j < 2; j++) {
            float4 a = aReg[j];
            if (MODE == 2) { a.x = hswish(a.x); a.y = hswish(a.y); a.z = hswish(a.z); a.w = hswish(a.w); }
            float av[4] = {a.x, a.y, a.z, a.w};
#pragma unroll
            for (int e = 0; e < 4; e++) {
                float h = tf32r(av[e]);
                Ah[lc4[j] * 4 + e][lrow[j]] = h;
                if (THREE) Al[lc4[j] * 4 + e][lrow[j]] = av[e] - h;
            }
            float4 b = bReg[j];
            float4 h4 = {tf32r(b.x), tf32r(b.y), tf32r(b.z), tf32r(b.w)};
            *(float4*)&Bh[bkr[j]][bnc[j]] = h4;
            if (THREE) {
                float4 lo = {b.x - h4.x, b.y - h4.y, b.z - h4.z, b.w - h4.w};
                *(float4*)&Bl[bkr[j]][bnc[j]] = lo;
            }
        }
        __syncthreads();

        if (t + 1 < NT) {
            int k0 = (t + 1) * 16;
#pragma unroll
            for (int j = 0; j < 2; j++) {
                aReg[j] = *(const float4*)(aptr[j] + k0);
                bReg[j] = *(const float4*)(bptr[j] + (size_t)k0 * N);
            }
        }

#pragma unroll
        for (int k8 = 0; k8 < 16; k8 += 8) {
            uint32_t ah[2][4], al[2][4];
#pragma unroll
            for (int mi = 0; mi < 2; mi++) {
                int r = wm * 32 + mi * 16 + g;
                ah[mi][0] = __float_as_uint(Ah[k8 + tg][r]);
                ah[mi][1] = __float_as_uint(Ah[k8 + tg][r + 8]);
                ah[mi][2] = __float_as_uint(Ah[k8 + tg + 4][r]);
                ah[mi][3] = __float_as_uint(Ah[k8 + tg + 4][r + 8]);
                if (THREE) {
                    al[mi][0] = __float_as_uint(Al[k8 + tg][r]);
                    al[mi][1] = __float_as_uint(Al[k8 + tg][r + 8]);
                    al[mi][2] = __float_as_uint(Al[k8 + tg + 4][r]);
                    al[mi][3] = __float_as_uint(Al[k8 + tg + 4][r + 8]);
                }
            }
#pragma unroll
            for (int nj = 0; nj < 8; nj++) {
                int n = wn * 64 + nj * 8 + g;
                uint32_t bh0 = __float_as_uint(Bh[k8 + tg][n]);
                uint32_t bh1 = __float_as_uint(Bh[k8 + tg + 4][n]);
#pragma unroll
                for (int mi = 0; mi < 2; mi++)
                    mma_tf32(acc[mi][nj][0], acc[mi][nj][1], acc[mi][nj][2], acc[mi][nj][3],
                             ah[mi][0], ah[mi][1], ah[mi][2], ah[mi][3], bh0, bh1);
                if (THREE) {
                    uint32_t bl0 = __float_as_uint(Bl[k8 + tg][n]);
                    uint32_t bl1 = __float_as_uint(Bl[k8 + tg + 4][n]);
#pragma unroll
                    for (int mi = 0; mi < 2; mi++) {
                        mma_tf32(acc[mi][nj][0], acc[mi][nj][1], acc[mi][nj][2], acc[mi][nj][3],
                                 ah[mi][0], ah[mi][1], ah[mi][2], ah[mi][3], bl0, bl1);
                        mma_tf32(acc[mi][nj][0], acc[mi][nj][1], acc[mi][nj][2], acc[mi][nj][3],
                                 al[mi][0], al[mi][1], al[mi][2], al[mi][3], bh0, bh1);
                    }
                }
            }
        }
        __syncthreads();
    }

    // epilogue with BN: out = acc*s + ((b-mu)*s + beta)
#pragma unroll
    for (int nj = 0; nj < 8; nj++) {
        int col = n0 + wn * 64 + nj * 8 + 2 * tg;
        float s0 = gam[col] * rsqrtf(var[col] + EPSB);
        float s1 = gam[col + 1] * rsqrtf(var[col + 1] + EPSB);
        float c0 = (bia[col] - mu[col]) * s0 + bet[col];
        float c1 = (bia[col + 1] - mu[col + 1]) * s1 + bet[col + 1];
#pragma unroll
        for (int mi = 0; mi < 2; mi++) {
            int row = m0 + wm * 32 + mi * 16 + g;
            float v00 = acc[mi][nj][0] * s0 + c0, v01 = acc[mi][nj][1] * s1 + c1;   // row
            float v10 = acc[mi][nj][2] * s0 + c0, v11 = acc[mi][nj][3] * s1 + c1;   // row+8
            if (MODE == 0) {
                int bb = row >> 12, seq = row & 4095;
                int hh = col / 80, c = col - hh * 80;
                if (c < KD) {
                    __nv_bfloat162 p0 = __floats2bfloat162_rn(v00, v01);
                    __nv_bfloat162 p1 = __floats2bfloat162_rn(v10, v11);
                    size_t kbase = ((size_t)(bb * HH + hh) * SEQL + seq) * KD + c;
                    *(__nv_bfloat162*)&d_Kb[kbase] = p0;
                    *(__nv_bfloat162*)&d_Kb[kbase + 8 * KD] = p1;
                } else {
                    int dd = c - KD;
                    size_t vbase = ((size_t)(bb * HH + hh) * VD + dd) * SEQL + seq;
                    d_Vt[vbase]            = __float2bfloat16_rn(v00);
                    d_Vt[vbase + SEQL]     = __float2bfloat16_rn(v01);
                    d_Vt[vbase + 8]        = __float2bfloat16_rn(v10);
                    d_Vt[vbase + SEQL + 8] = __float2bfloat16_rn(v11);
                }
            } else {
                float* C = (MODE == 1) ? d_qbuf : Cout;
                float2 o0 = {v00, v01};
                float2 o1 = {v10, v11};
                *(float2*)(C + (size_t)row * N + col) = o0;
                *(float2*)(C + (size_t)(row + 8) * N + col) = o1;
            }
        }
    }
}

// ---------------------------------------------------------------------------
// Flash attention via bf16 mma.sync (m16n8k16), 2 query-tiles per block.
// Block = (b, h, 128 queries): 4 warps; warp w handles q-rows q0+w*16.. (set 0)
// and q0+64+w*16.. (set 1). K/V fragments loaded once, used by both sets.
// 32-key tiles, cp.async double-buffered. No online max; softmax in base 2.
// K tile [32][24] bf16 (48B rows), V tile [64][40] bf16 (80B rows) — both
// conflict-free for the LDS.32 fragment patterns.
// Output pre-reshaped: Z[b][h*128 + 2d + (q>>9)][q&511] = av[b,h,q,d]
// ---------------------------------------------------------------------------
__global__ __launch_bounds__(128) void attn_kernel() {
    __shared__ __align__(16) __nv_bfloat16 Ks[2][32][24];
    __shared__ __align__(16) __nv_bfloat16 Vs[2][64][40];

    int tid = threadIdx.x;
    int b = blockIdx.z, h = blockIdx.y;
    int q0 = blockIdx.x * 128;
    int w = tid >> 5;
    int lane = tid & 31;
    int g = lane >> 2, tg = lane & 3;

    const __nv_bfloat16* Kg = d_Kb + (size_t)(b * HH + h) * SEQL * KD;
    const __nv_bfloat16* Vg = d_Vt + (size_t)(b * HH + h) * VD * SEQL;

    const __nv_bfloat16* kgp = nullptr;
    uint32_t ksm[2] = {0, 0};
    if (tid < 64) {
        int r = tid >> 1, o = (tid & 1) * 8;
        kgp = Kg + (size_t)r * KD + o;
        ksm[0] = s2u(&Ks[0][r][o]);
        ksm[1] = s2u(&Ks[1][r][o]);
    }
    const __nv_bfloat16* vgp[2];
    uint32_t vsm[2][2];
#pragma unroll
    for (int j = 0; j < 2; j++) {
        int idx = tid + j * 128;
        int r = idx >> 2, o = (idx & 3) * 8;
        vgp[j] = Vg + (size_t)r * SEQL + o;
        vsm[0][j] = s2u(&Vs[0][r][o]);
        vsm[1][j] = s2u(&Vs[1][r][o]);
    }

    const float SC = 0.25f * 1.44269504088896340736f;
    int qA = q0 + w * 16 + g;       // set 0, row g
    int qB = qA + 8;                // set 0, row g+8
    int qC = qA + 64;               // set 1
    int qD = qB + 64;
    const float* qpA = d_qbuf + (size_t)(b * QL + qA) * QD + h * KD;
    const float* qpB = d_qbuf + (size_t)(b * QL + qB) * QD + h * KD;
    const float* qpC = qpA + (size_t)64 * QD;
    const float* qpD = qpB + (size_t)64 * QD;
    uint32_t qa0[4], qa1[4];
    qa0[0] = packbf(qpA[2 * tg] * SC,     qpA[2 * tg + 1] * SC);
    qa0[1] = packbf(qpB[2 * tg] * SC,     qpB[2 * tg + 1] * SC);
    qa0[2] = packbf(qpA[8 + 2 * tg] * SC, qpA[8 + 2 * tg + 1] * SC);
    qa0[3] = packbf(qpB[8 + 2 * tg] * SC, qpB[8 + 2 * tg + 1] * SC);
    qa1[0] = packbf(qpC[2 * tg] * SC,     qpC[2 * tg + 1] * SC);
    qa1[1] = packbf(qpD[2 * tg] * SC,     qpD[2 * tg + 1] * SC);
    qa1[2] = packbf(qpC[8 + 2 * tg] * SC, qpC[8 + 2 * tg + 1] * SC);
    qa1[3] = packbf(qpD[8 + 2 * tg] * SC, qpD[8 + 2 * tg + 1] * SC);

    float acc0[8][4], acc1[8][4];
#pragma unroll
    for (int i = 0; i < 8; i++)
#pragma unroll
        for (int j = 0; j < 4; j++) { acc0[i][j] = 0.0f; acc1[i][j] = 0.0f; }
    float l00 = 0.0f, l01 = 0.0f, l10 = 0.0f, l11 = 0.0f;

    if (tid < 64) cpasync16(ksm[0], kgp);
#pragma unroll
    for (int j = 0; j < 2; j++) cpasync16(vsm[0][j], vgp[j]);
    CP_COMMIT();

    const int NT = SEQL / 32;
    for (int t = 0; t < NT; ++t) {
        if (t + 1 < NT) {
            int koff = (t + 1) * 32;
            int nbf = (t + 1) & 1;
            if (tid < 64) cpasync16(ksm[nbf], kgp + (size_t)koff * KD);
#pragma unroll
            for (int j = 0; j < 2; j++) cpasync16(vsm[nbf][j], vgp[j] + koff);
        }
        CP_COMMIT();
        CP_WAIT1();
        __syncthreads();

        const int bf = t & 1;
#pragma unroll
        for (int kg16 = 0; kg16 < 2; kg16++) {
            const int kr = kg16 * 16;
            uint32_t kb0 = *(const uint32_t*)&Ks[bf][kr + g][2 * tg];
            uint32_t kb1 = *(const uint32_t*)&Ks[bf][kr + g][8 + 2 * tg];
            uint32_t kb2 = *(const uint32_t*)&Ks[bf][kr + 8 + g][2 * tg];
            uint32_t kb3 = *(const uint32_t*)&Ks[bf][kr + 8 + g][8 + 2 * tg];

            // set 0 scores
            float c0 = 0.f, c1 = 0.f, c2 = 0.f, c3 = 0.f;
            mma_bf16(c0, c1, c2, c3, qa0[0], qa0[1], qa0[2], qa0[3], kb0, kb1);
            float d0 = 0.f, d1 = 0.f, d2 = 0.f, d3 = 0.f;
            mma_bf16(d0, d1, d2, d3, qa0[0], qa0[1], qa0[2], qa0[3], kb2, kb3);
            // set 1 scores
            float e0 = 0.f, e1 = 0.f, e2 = 0.f, e3 = 0.f;
            mma_bf16(e0, e1, e2, e3, qa1[0], qa1[1], qa1[2], qa1[3], kb0, kb1);
            float f0 = 0.f, f1 = 0.f, f2 = 0.f, f3 = 0.f;
            mma_bf16(f0, f1, f2, f3, qa1[0], qa1[1], qa1[2], qa1[3], kb2, kb3);

            float p00 = ex2(c0), p01 = ex2(c1), p02 = ex2(c2), p03 = ex2(c3);
            float p10 = ex2(d0), p11 = ex2(d1), p12 = ex2(d2), p13 = ex2(d3);
            float r00 = ex2(e0), r01 = ex2(e1), r02 = ex2(e2), r03 = ex2(e3);
            float r10 = ex2(f0), r11 = ex2(f1), r12 = ex2(f2), r13 = ex2(f3);
            l00 += (p00 + p01) + (p10 + p11);
            l01 += (p02 + p03) + (p12 + p13);
            l10 += (r00 + r01) + (r10 + r11);
            l11 += (r02 + r03) + (r12 + r13);

            uint32_t a0 = packbf(p00, p01), a1 = packbf(p02, p03);
            uint32_t a2 = packbf(p10, p11), a3 = packbf(p12, p13);
            uint32_t b0 = packbf(r00, r01), b1 = packbf(r02, r03);
            uint32_t b2 = packbf(r10, r11), b3 = packbf(r12, r13);
#pragma unroll
            for (int nt = 0; nt < 8; nt++) {
                uint32_t vb0 = *(const uint32_t*)&Vs[bf][8 * nt + g][kr + 2 * tg];
                uint32_t vb1 = *(const uint32_t*)&Vs[bf][8 * nt + g][kr + 8 + 2 * tg];
                mma_bf16(acc0[nt][0], acc0[nt][1], acc0[nt][2], acc0[nt][3],
                         a0, a1, a2, a3, vb0, vb1);
                mma_bf16(acc1[nt][0], acc1[nt][1], acc1[nt][2], acc1[nt][3],
                         b0, b1, b2, b3, vb0, vb1);
            }
        }
        __syncthreads();
    }

    l00 += __shfl_xor_sync(0xffffffffu, l00, 1);
    l00 += __shfl_xor_sync(0xffffffffu, l00, 2);
    l01 += __shfl_xor_sync(0xffffffffu, l01, 1);
    l01 += __shfl_xor_sync(0xffffffffu, l01, 2);
    l10 += __shfl_xor_sync(0xffffffffu, l10, 1);
    l10 += __shfl_xor_sync(0xffffffffu, l10, 2);
    l11 += __shfl_xor_sync(0xffffffffu, l11, 1);
    l11 += __shfl_xor_sync(0xffffffffu, l11, 2);
    float rA = 1.0f / l00, rB = 1.0f / l01, rC = 1.0f / l10, rD = 1.0f / l11;

    float* zb = d_zbuf + (size_t)b * QL * COUT;
    int colA = qA & 511, hiA = qA >> 9;
    int colB = qB & 511, hiB = qB >> 9;
    int colC = qC & 511, hiC = qC >> 9;
    int colD = qD & 511, hiD = qD >> 9;
#pragma unroll
    for (int nt = 0; nt < 8; nt++) {
#pragma unroll
        for (int e = 0; e < 2; e++) {
            int d = 8 * nt + 2 * tg + e;
            size_t rowoff = (size_t)(h * 128 + 2 * d) * COUT;
            zb[rowoff + (size_t)hiA * COUT + colA] = acc0[nt][e] * rA;
            zb[rowoff + (size_t)hiB * COUT + colB] = acc0[nt][2 + e] * rB;
            zb[rowoff + (size_t)hiC * COUT + colC] = acc1[nt][e] * rC;
            zb[rowoff + (size_t)hiD * COUT + colD] = acc1[nt][2 + e] * rD;
        }
    }
}

// ---------------------------------------------------------------------------
// Launch
// ---------------------------------------------------------------------------
extern "C" void kernel_launch(void* const* d_in, const int* in_sizes, int n_in,
                              void* d_out, int out_size) {
    const float* x    = (const float*)d_in[0];
    const float* Wkv  = (const float*)d_in[1];
    const float* bkv  = (const float*)d_in[2];
    const float* gkv  = (const float*)d_in[3];
    const float* bekv = (const float*)d_in[4];
    const float* mkv  = (const float*)d_in[5];
    const float* vkv  = (const float*)d_in[6];
    const float* Wq   = (const float*)d_in[7];
    const float* bq   = (const float*)d_in[8];
    const float* gq   = (const float*)d_in[9];
    const float* beq  = (const float*)d_in[10];
    const float* mq   = (const float*)d_in[11];
    const float* vq   = (const float*)d_in[12];
    const float* Wp   = (const float*)d_in[13];
    const float* bp   = (const float*)d_in[14];
    const float* gp   = (const float*)d_in[15];
    const float* bep  = (const float*)d_in[16];
    const float* mp   = (const float*)d_in[17];
    const float* vp   = (const float*)d_in[18];
    float* out = (float*)d_out;

    // kv = BN(x @ Wkv + b) -> K (bf16) + V-transposed (bf16)
    tgemm_kernel<0, 0><<<dim3(KVD / 128, (BB * SEQL) / 128), 256>>>(
        x, Wkv, bkv, gkv, bekv, mkv, vkv, nullptr, BB * SEQL, KVD, CIN);
    // q = BN(xq @ Wq + b) -> fp32
    tgemm_kernel<1, 0><<<dim3(QD / 128, (BB * QL) / 128), 256>>>(
        x, Wq, bq, gq, beq, mq, vq, nullptr, BB * QL, QD, CIN);
    // fused flash attention (bf16 mma, 2 q-tiles/block) -> d_zbuf
    attn_kernel<<<dim3(QL / 128, HH, BB), 128>>>();
    // out = BN(hswish(zbuf) @ Wp + b), 3xTF32; A selected device-side
    tgemm_kernel<2, 1><<<dim3(COUT / 128, (BB * QL) / 128), 256>>>(
        nullptr, Wp, bp, gp, bep, mp, vp, out, BB * QL, COUT, COUT);
}

// round 17
// speedup vs baseline: 1.1426x; 1.1119x over previous
#include <cuda_runtime.h>
#include <cuda_bf16.h>
#include <math.h>
#include <stdint.h>

// Problem constants
#define BB   8
#define SEQL 4096
#define QL   1024
#define CIN  256
#define KVD  640
#define QD   128
#define HH   8
#define KD   16
#define VD   64
#define COUT 512
#define EPSB 1e-3f

// Intermediates as __device__ globals (no dynamic allocation allowed)
__device__ __nv_bfloat16 d_Kb[BB * HH * SEQL * KD];   // K bf16 [b][h][seq][16]
__device__ __nv_bfloat16 d_Vt[BB * HH * VD * SEQL];   // V bf16 transposed [b][h][dim][seq]
__device__ float d_qbuf [BB * QL * QD];               // [B, QLEN, 128] (BN folded)
__device__ float d_zbuf [BB * QL * COUT];             // attention out, TF-reshaped

__device__ __forceinline__ float ex2(float x) {
    float y;
    asm("ex2.approx.ftz.f32 %0, %1;" : "=f"(y) : "f"(x));
    return y;
}
__device__ __forceinline__ uint32_t s2u(const void* p) {
    return (uint32_t)__cvta_generic_to_shared(p);
}
__device__ __forceinline__ void cpasync16(uint32_t dst, const void* src) {
    asm volatile("cp.async.cg.shared.global [%0], [%1], 16;" :: "r"(dst), "l"(src));
}
#define CP_COMMIT() asm volatile("cp.async.commit_group;")
#define CP_WAIT1()  asm volatile("cp.async.wait_group 1;")

__device__ __forceinline__ uint32_t f2tf32(float x) {
    uint32_t r;
    asm("cvt.rna.tf32.f32 %0, %1;" : "=r"(r) : "f"(x));
    return r;
}
__device__ __forceinline__ float tf32r(float x) {
    return __uint_as_float(f2tf32(x));
}
// m16n8k8 tf32 MMA, D = A*B + D
__device__ __forceinline__ void mma_tf32(float& c0, float& c1, float& c2, float& c3,
                                         uint32_t a0, uint32_t a1, uint32_t a2, uint32_t a3,
                                         uint32_t b0, uint32_t b1) {
    asm volatile("mma.sync.aligned.m16n8k8.row.col.f32.tf32.tf32.f32 "
                 "{%0,%1,%2,%3}, {%4,%5,%6,%7}, {%8,%9}, {%0,%1,%2,%3};"
                 : "+f"(c0), "+f"(c1), "+f"(c2), "+f"(c3)
                 : "r"(a0), "r"(a1), "r"(a2), "r"(a3), "r"(b0), "r"(b1));
}
// m16n8k16 bf16 MMA, D = A*B + D
__device__ __forceinline__ void mma_bf16(float& c0, float& c1, float& c2, float& c3,
                                         uint32_t a0, uint32_t a1, uint32_t a2, uint32_t a3,
                                         uint32_t b0, uint32_t b1) {
    asm volatile("mma.sync.aligned.m16n8k16.row.col.f32.bf16.bf16.f32 "
                 "{%0,%1,%2,%3}, {%4,%5,%6,%7}, {%8,%9}, {%0,%1,%2,%3};"
                 : "+f"(c0), "+f"(c1), "+f"(c2), "+f"(c3)
                 : "r"(a0), "r"(a1), "r"(a2), "r"(a3), "r"(b0), "r"(b1));
}
__device__ __forceinline__ uint32_t packbf(float lo, float hi) {
    __nv_bfloat162 p = __floats2bfloat162_rn(lo, hi);
    return *(uint32_t*)&p;
}
__device__ __forceinline__ float hswish(float x) {
    return x * __saturatef(x * (1.0f / 6.0f) + 0.5f);
}

// ---------------------------------------------------------------------------
// tf32 tensor-core GEMM, register-prefetch pipelined, BN in epilogue.
// BM=128, BN=128, BK=16, 256 threads (8 warps: 4m x 2n, warp tile 32x64).
// Smem rows padded to 136 floats (136 mod 32 = 8) => fragment-load bank
//   = 8*tg + g : all 32 banks distinct (132-pad gave 2-way conflicts).
// A tile additionally column-skewed: element (k, r) stored at column
//   (r + 8*(k>>2)) & 127, making the staging STS conflict-free too.
// MODE 0: kv (A=Ain=x) -> scatter K (bf16) + V-transposed (bf16).
// MODE 1: q (A=Ain=x strided gather) -> d_qbuf fp32.
// MODE 2: proj (A = d_zbuf selected device-side, hswish), THREE=1 (3xTF32).
// ---------------------------------------------------------------------------
template <int MODE, int THREE>
__global__ __launch_bounds__(256, 2) void tgemm_kernel(const float* __restrict__ Ain,
                                                       const float* __restrict__ W,
                                                       const float* __restrict__ bia,
                                                       const float* __restrict__ gam,
                                                       const float* __restrict__ bet,
                                                       const float* __restrict__ mu,
                                                       const float* __restrict__ var,
                                                       float* __restrict__ Cout,
                                                       int M, int N, int K) {
    const float* A = (MODE == 2) ? d_zbuf : Ain;

    __shared__ __align__(16) float Ah[16][136];
    __shared__ __align__(16) float Bh[16][136];
    __shared__ __align__(16) float Al[THREE ? 16 : 1][THREE ? 136 : 4];
    __shared__ __align__(16) float Bl[THREE ? 16 : 1][THREE ? 136 : 4];

    int tid  = threadIdx.x;
    int m0 = blockIdx.y * 128;
    int n0 = blockIdx.x * 128;
    int w = tid >> 5, lane = tid & 31;
    int g = lane >> 2, tg = lane & 3;
    int wm = w >> 1, wn = w & 1;

    float acc[2][8][4];
#pragma unroll
    for (int i = 0; i < 2; i++)
#pragma unroll
        for (int j = 0; j < 8; j++)
#pragma unroll
            for (int e = 0; e < 4; e++) acc[i][j][e] = 0.0f;

    int lrow[2], lc4[2];
    const float* aptr[2];
#pragma unroll
    for (int j = 0; j < 2; j++) {
        int idx = tid + j * 256;
        int r = idx >> 2, c4 = idx & 3;
        lrow[j] = r; lc4[j] = c4;
        int gr = m0 + r;
        int src;
        if (MODE == 1) {
            int bb = gr >> 10, ql = gr & 1023;
            int qy = ql >> 5, qx = ql & 31;
            src = (bb << 12) + (qy << 7) + (qx << 1);
        } else {
            src = gr;
        }
        aptr[j] = A + (size_t)src * K + c4 * 4;
    }
    int bkr[2], bnc[2];
    const float* bptr[2];
#pragma unroll
    for (int j = 0; j < 2; j++) {
        int idx = tid + j * 256;
        bkr[j] = idx >> 5; bnc[j] = (idx & 31) * 4;
        bptr[j] = W + (size_t)bkr[j] * N + n0 + bnc[j];
    }

    float4 aReg[2], bReg[2];
#pragma unroll
    for (int j = 0; j < 2; j++) {
        aReg[j] = *(const float4*)(aptr[j]);
        bReg[j] = *(const float4*)(bptr[j]);
    }

    const int NT = K / 16;
    for (int t = 0; t < NT; ++t) {
#pragma unroll
        for (int j = 0; j < 2; j++) {
            float4 a = aReg[j];
            if (MODE == 2) { a.x = hswish(a.x); a.y = hswish(a.y); a.z = hswish(a.z); a.w = hswish(a.w); }
            float av[4] = {a.x, a.y, a.z, a.w};
            int scol = (lrow[j] + 8 * lc4[j]) & 127;   // skew col by 8*(k>>2), k=4*lc4+e
#pragma unroll
            for (int e = 0; e < 4; e++) {
                float h = tf32r(av[e]);
                Ah[lc4[j] * 4 + e][scol] = h;
                if (THREE) Al[lc4[j] * 4 + e][scol] = av[e] - h;
            }
            float4 b = bReg[j];
            float4 h4 = {tf32r(b.x), tf32r(b.y), tf32r(b.z), tf32r(b.w)};
            *(float4*)&Bh[bkr[j]][bnc[j]] = h4;
            if (THREE) {
                float4 lo = {b.x - h4.x, b.y - h4.y, b.z - h4.z, b.w - h4.w};
                *(float4*)&Bl[bkr[j]][bnc[j]] = lo;
            }
        }
        __syncthreads();

        if (t + 1 < NT) {
            int k0 = (t + 1) * 16;
#pragma unroll
            for (int j = 0; j < 2; j++) {
                aReg[j] = *(const float4*)(aptr[j] + k0);
                bReg[j] = *(const float4*)(bptr[j] + (size_t)k0 * N);
            }
        }

#pragma unroll
        for (int k8 = 0; k8 < 16; k8 += 8) {
            // A-row skew constants: rows k8+tg (k>>2 = k8/4) and k8+tg+4 (k8/4+1)
            const int sk0 = k8 * 2;        // 8*(k8>>2)
            const int sk1 = sk0 + 8;
            uint32_t ah[2][4], al[2][4];
#pragma unroll
            for (int mi = 0; mi < 2; mi++) {
                int r = wm * 32 + mi * 16 + g;
                int c0a = (r + sk0) & 127, c0b = (r + 8 + sk0) & 127;
                int c1a = (r + sk1) & 127, c1b = (r + 8 + sk1) & 127;
                ah[mi][0] = __float_as_uint(Ah[k8 + tg][c0a]);
                ah[mi][1] = __float_as_uint(Ah[k8 + tg][c0b]);
                ah[mi][2] = __float_as_uint(Ah[k8 + tg + 4][c1a]);
                ah[mi][3] = __float_as_uint(Ah[k8 + tg + 4][c1b]);
                if (THREE) {
                    al[mi][0] = __float_as_uint(Al[k8 + tg][c0a]);
                    al[mi][1] = __float_as_uint(Al[k8 + tg][c0b]);
                    al[mi][2] = __float_as_uint(Al[k8 + tg + 4][c1a]);
                    al[mi][3] = __float_as_uint(Al[k8 + tg + 4][c1b]);
                }
            }
#pragma unroll
            for (int nj = 0; nj < 8; nj++) {
                int n = wn * 64 + nj * 8 + g;
                uint32_t bh0 = __float_as_uint(Bh[k8 + tg][n]);
                uint32_t bh1 = __float_as_uint(Bh[k8 + tg + 4][n]);
#pragma unroll
                for (int mi = 0; mi < 2; mi++)
                    mma_tf32(acc[mi][nj][0], acc[mi][nj][1], acc[mi][nj][2], acc[mi][nj][3],
                             ah[mi][0], ah[mi][1], ah[mi][2], ah[mi][3], bh0, bh1);
                if (THREE) {
                    uint32_t bl0 = __float_as_uint(Bl[k8 + tg][n]);
                    uint32_t bl1 = __float_as_uint(Bl[k8 + tg + 4][n]);
#pragma unroll
                    for (int mi = 0; mi < 2; mi++) {
                        mma_tf32(acc[mi][nj][0], acc[mi][nj][1], acc[mi][nj][2], acc[mi][nj][3],
                                 ah[mi][0], ah[mi][1], ah[mi][2], ah[mi][3], bl0, bl1);
                        mma_tf32(acc[mi][nj][0], acc[mi][nj][1], acc[mi][nj][2], acc[mi][nj][3],
                                 al[mi][0], al[mi][1], al[mi][2], al[mi][3], bh0, bh1);
                    }
                }
            }
        }
        __syncthreads();
    }

    // epilogue with BN: out = acc*s + ((b-mu)*s + beta)
#pragma unroll
    for (int nj = 0; nj < 8; nj++) {
        int col = n0 + wn * 64 + nj * 8 + 2 * tg;
        float s0 = gam[col] * rsqrtf(var[col] + EPSB);
        float s1 = gam[col + 1] * rsqrtf(var[col + 1] + EPSB);
        float c0 = (bia[col] - mu[col]) * s0 + bet[col];
        float c1 = (bia[col + 1] - mu[col + 1]) * s1 + bet[col + 1];
#pragma unroll
        for (int mi = 0; mi < 2; mi++) {
            int row = m0 + wm * 32 + mi * 16 + g;
            float v00 = acc[mi][nj][0] * s0 + c0, v01 = acc[mi][nj][1] * s1 + c1;   // row
            float v10 = acc[mi][nj][2] * s0 + c0, v11 = acc[mi][nj][3] * s1 + c1;   // row+8
            if (MODE == 0) {
                int bb = row >> 12, seq = row & 4095;
                int hh = col / 80, c = col - hh * 80;
                if (c < KD) {
                    __nv_bfloat162 p0 = __floats2bfloat162_rn(v00, v01);
                    __nv_bfloat162 p1 = __floats2bfloat162_rn(v10, v11);
                    size_t kbase = ((size_t)(bb * HH + hh) * SEQL + seq) * KD + c;
                    *(__nv_bfloat162*)&d_Kb[kbase] = p0;
                    *(__nv_bfloat162*)&d_Kb[kbase + 8 * KD] = p1;
                } else {
                    int dd = c - KD;
                    size_t vbase = ((size_t)(bb * HH + hh) * VD + dd) * SEQL + seq;
                    d_Vt[vbase]            = __float2bfloat16_rn(v00);
                    d_Vt[vbase + SEQL]     = __float2bfloat16_rn(v01);
                    d_Vt[vbase + 8]        = __float2bfloat16_rn(v10);
                    d_Vt[vbase + SEQL + 8] = __float2bfloat16_rn(v11);
                }
            } else {
                float* C = (MODE == 1) ? d_qbuf : Cout;
                float2 o0 = {v00, v01};
                float2 o1 = {v10, v11};
                *(float2*)(C + (size_t)row * N + col) = o0;
                *(float2*)(C + (size_t)(row + 8) * N + col) = o1;
            }
        }
    }
}

// ---------------------------------------------------------------------------
// Flash attention via bf16 mma.sync (m16n8k16), 2 query-tiles per block.
// (unchanged from R15 — proven)
// ---------------------------------------------------------------------------
__global__ __launch_bounds__(128) void attn_kernel() {
    __shared__ __align__(16) __nv_bfloat16 Ks[2][32][24];
    __shared__ __align__(16) __nv_bfloat16 Vs[2][64][40];

    int tid = threadIdx.x;
    int b = blockIdx.z, h = blockIdx.y;
    int q0 = blockIdx.x * 128;
    int w = tid >> 5;
    int lane = tid & 31;
    int g = lane >> 2, tg = lane & 3;

    const __nv_bfloat16* Kg = d_Kb + (size_t)(b * HH + h) * SEQL * KD;
    const __nv_bfloat16* Vg = d_Vt + (size_t)(b * HH + h) * VD * SEQL;

    const __nv_bfloat16* kgp = nullptr;
    uint32_t ksm[2] = {0, 0};
    if (tid < 64) {
        int r = tid >> 1, o = (tid & 1) * 8;
        kgp = Kg + (size_t)r * KD + o;
        ksm[0] = s2u(&Ks[0][r][o]);
        ksm[1] = s2u(&Ks[1][r][o]);
    }
    const __nv_bfloat16* vgp[2];
    uint32_t vsm[2][2];
#pragma unroll
    for (int j = 0; j < 2; j++) {
        int idx = tid + j * 128;
        int r = idx >> 2, o = (idx & 3) * 8;
        vgp[j] = Vg + (size_t)r * SEQL + o;
        vsm[0][j] = s2u(&Vs[0][r][o]);
        vsm[1][j] = s2u(&Vs[1][r][o]);
    }

    const float SC = 0.25f * 1.44269504088896340736f;
    int qA = q0 + w * 16 + g;
    int qB = qA + 8;
    int qC = qA + 64;
    int qD = qB + 64;
    const float* qpA = d_qbuf + (size_t)(b * QL + qA) * QD + h * KD;
    const float* qpB = d_qbuf + (size_t)(b * QL + qB) * QD + h * KD;
    const float* qpC = qpA + (size_t)64 * QD;
    const float* qpD = qpB + (size_t)64 * QD;
    uint32_t qa0[4], qa1[4];
    qa0[0] = packbf(qpA[2 * tg] * SC,     qpA[2 * tg + 1] * SC);
    qa0[1] = packbf(qpB[2 * tg] * SC,     qpB[2 * tg + 1] * SC);
    qa0[2] = packbf(qpA[8 + 2 * tg] * SC, qpA[8 + 2 * tg + 1] * SC);
    qa0[3] = packbf(qpB[8 + 2 * tg] * SC, qpB[8 + 2 * tg + 1] * SC);
    qa1[0] = packbf(qpC[2 * tg] * SC,     qpC[2 * tg + 1] * SC);
    qa1[1] = packbf(qpD[2 * tg] * SC,     qpD[2 * tg + 1] * SC);
    qa1[2] = packbf(qpC[8 + 2 * tg] * SC, qpC[8 + 2 * tg + 1] * SC);
    qa1[3] = packbf(qpD[8 + 2 * tg] * SC, qpD[8 + 2 * tg + 1] * SC);

    float acc0[8][4], acc1[8][4];
#pragma unroll
    for (int i = 0; i < 8; i++)
#pragma unroll
        for (int j = 0; j < 4; j++) { acc0[i][j] = 0.0f; acc1[i][j] = 0.0f; }
    float l00 = 0.0f, l01 = 0.0f, l10 = 0.0f, l11 = 0.0f;

    if (tid < 64) cpasync16(ksm[0], kgp);
#pragma unroll
    for (int j = 0; j < 2; j++) cpasync16(vsm[0][j], vgp[j]);
    CP_COMMIT();

    const int NT = SEQL / 32;
    for (int t = 0; t < NT; ++t) {
        if (t + 1 < NT) {
            int koff = (t + 1) * 32;
            int nbf = (t + 1) & 1;
            if (tid < 64) cpasync16(ksm[nbf], kgp + (size_t)koff * KD);
#pragma unroll
            for (int j = 0; j < 2; j++) cpasync16(vsm[nbf][j], vgp[j] + koff);
        }
        CP_COMMIT();
        CP_WAIT1();
        __syncthreads();

        const int bf = t & 1;
#pragma unroll
        for (int kg16 = 0; kg16 < 2; kg16++) {
            const int kr = kg16 * 16;
            uint32_t kb0 = *(const uint32_t*)&Ks[bf][kr + g][2 * tg];
            uint32_t kb1 = *(const uint32_t*)&Ks[bf][kr + g][8 + 2 * tg];
            uint32_t kb2 = *(const uint32_t*)&Ks[bf][kr + 8 + g][2 * tg];
            uint32_t kb3 = *(const uint32_t*)&Ks[bf][kr + 8 + g][8 + 2 * tg];

            float c0 = 0.f, c1 = 0.f, c2 = 0.f, c3 = 0.f;
            mma_bf16(c0, c1, c2, c3, qa0[0], qa0[1], qa0[2], qa0[3], kb0, kb1);
            float d0 = 0.f, d1 = 0.f, d2 = 0.f, d3 = 0.f;
            mma_bf16(d0, d1, d2, d3, qa0[0], qa0[1], qa0[2], qa0[3], kb2, kb3);
            float e0 = 0.f, e1 = 0.f, e2 = 0.f, e3 = 0.f;
            mma_bf16(e0, e1, e2, e3, qa1[0], qa1[1], qa1[2], qa1[3], kb0, kb1);
            float f0 = 0.f, f1 = 0.f, f2 = 0.f, f3 = 0.f;
            mma_bf16(f0, f1, f2, f3, qa1[0], qa1[1], qa1[2], qa1[3], kb2, kb3);

            float p00 = ex2(c0), p01 = ex2(c1), p02 = ex2(c2), p03 = ex2(c3);
            float p10 = ex2(d0), p11 = ex2(d1), p12 = ex2(d2), p13 = ex2(d3);
            float r00 = ex2(e0), r01 = ex2(e1), r02 = ex2(e2), r03 = ex2(e3);
            float r10 = ex2(f0), r11 = ex2(f1), r12 = ex2(f2), r13 = ex2(f3);
            l00 += (p00 + p01) + (p10 + p11);
            l01 += (p02 + p03) + (p12 + p13);
            l10 += (r00 + r01) + (r10 + r11);
            l11 += (r02 + r03) + (r12 + r13);

            uint32_t a0 = packbf(p00, p01), a1 = packbf(p02, p03);
            uint32_t a2 = packbf(p10, p11), a3 = packbf(p12, p13);
            uint32_t b0 = packbf(r00, r01), b1 = packbf(r02, r03);
            uint32_t b2 = packbf(r10, r11), b3 = packbf(r12, r13);
#pragma unroll
            for (int nt = 0; nt < 8; nt++) {
                uint32_t vb0 = *(const uint32_t*)&Vs[bf][8 * nt + g][kr + 2 * tg];
                uint32_t vb1 = *(const uint32_t*)&Vs[bf][8 * nt + g][kr + 8 + 2 * tg];
                mma_bf16(acc0[nt][0], acc0[nt][1], acc0[nt][2], acc0[nt][3],
                         a0, a1, a2, a3, vb0, vb1);
                mma_bf16(acc1[nt][0], acc1[nt][1], acc1[nt][2], acc1[nt][3],
                         b0, b1, b2, b3, vb0, vb1);
            }
        }
        __syncthreads();
    }

    l00 += __shfl_xor_sync(0xffffffffu, l00, 1);
    l00 += __shfl_xor_sync(0xffffffffu, l00, 2);
    l01 += __shfl_xor_sync(0xffffffffu, l01, 1);
    l01 += __shfl_xor_sync(0xffffffffu, l01, 2);
    l10 += __shfl_xor_sync(0xffffffffu, l10, 1);
    l10 += __shfl_xor_sync(0xffffffffu, l10, 2);
    l11 += __shfl_xor_sync(0xffffffffu, l11, 1);
    l11 += __shfl_xor_sync(0xffffffffu, l11, 2);
    float rA = 1.0f / l00, rB = 1.0f / l01, rC = 1.0f / l10, rD = 1.0f / l11;

    float* zb = d_zbuf + (size_t)b * QL * COUT;
    int colA = qA & 511, hiA = qA >> 9;
    int colB = qB & 511, hiB = qB >> 9;
    int colC = qC & 511, hiC = qC >> 9;
    int colD = qD & 511, hiD = qD >> 9;
#pragma unroll
    for (int nt = 0; nt < 8; nt++) {
#pragma unroll
        for (int e = 0; e < 2; e++) {
            int d = 8 * nt + 2 * tg + e;
            size_t rowoff = (size_t)(h * 128 + 2 * d) * COUT;
            zb[rowoff + (size_t)hiA * COUT + colA] = acc0[nt][e] * rA;
            zb[rowoff + (size_t)hiB * COUT + colB] = acc0[nt][2 + e] * rB;
            zb[rowoff + (size_t)hiC * COUT + colC] = acc1[nt][e] * rC;
            zb[rowoff + (size_t)hiD * COUT + colD] = acc1[nt][2 + e] * rD;
        }
    }
}

// ---------------------------------------------------------------------------
// Launch
// ---------------------------------------------------------------------------
extern "C" void kernel_launch(void* const* d_in, const int* in_sizes, int n_in,
                              void* d_out, int out_size) {
    const float* x    = (const float*)d_in[0];
    const float* Wkv  = (const float*)d_in[1];
    const float* bkv  = (const float*)d_in[2];
    const float* gkv  = (const float*)d_in[3];
    const float* bekv = (const float*)d_in[4];
    const float* mkv  = (const float*)d_in[5];
    const float* vkv  = (const float*)d_in[6];
    const float* Wq   = (const float*)d_in[7];
    const float* bq   = (const float*)d_in[8];
    const float* gq   = (const float*)d_in[9];
    const float* beq  = (const float*)d_in[10];
    const float* mq   = (const float*)d_in[11];
    const float* vq   = (const float*)d_in[12];
    const float* Wp   = (const float*)d_in[13];
    const float* bp   = (const float*)d_in[14];
    const float* gp   = (const float*)d_in[15];
    const float* bep  = (const float*)d_in[16];
    const float* mp   = (const float*)d_in[17];
    const float* vp   = (const float*)d_in[18];
    float* out = (float*)d_out;

    // kv = BN(x @ Wkv + b) -> K (bf16) + V-transposed (bf16)
    tgemm_kernel<0, 0><<<dim3(KVD / 128, (BB * SEQL) / 128), 256>>>(
        x, Wkv, bkv, gkv, bekv, mkv, vkv, nullptr, BB * SEQL, KVD, CIN);
    // q = BN(xq @ Wq + b) -> fp32
    tgemm_kernel<1, 0><<<dim3(QD / 128, (BB * QL) / 128), 256>>>(
        x, Wq, bq, gq, beq, mq, vq, nullptr, BB * QL, QD, CIN);
    // fused flash attention (bf16 mma, 2 q-tiles/block) -> d_zbuf
    attn_kernel<<<dim3(QL / 128, HH, BB), 128>>>();
    // out = BN(hswish(zbuf) @ Wp + b), 3xTF32; A selected device-side
    tgemm_kernel<2, 1><<<dim3(COUT / 128, (BB * QL) / 128), 256>>>(
        nullptr, Wp, bp, gp, bep, mp, vp, out, BB * QL, COUT, COUT);
}